// round 12
// baseline (speedup 1.0000x reference)
#include <cuda_runtime.h>
#include <cstdint>

#define Hc 224
#define Wc 224
#define Cc 96
#define CPc 48          // channel pairs (float2 as ull)
#define TAPS 49
#define WT 8            // per-thread output width (float2 cols)
#define HT 4            // per-thread output height

typedef unsigned long long ull;

// Flipped kernel, transposed to [tap][cp] packed float2
__device__ ull g_wT[TAPS * CPc];

__global__ void prep_kernel(const float* __restrict__ k) {
    int idx = blockIdx.x * blockDim.x + threadIdx.x;
    if (idx < TAPS * Cc) {
        int tap = idx / Cc, c = idx % Cc;
        int i = tap / 7, j = tap % 7;
        reinterpret_cast<float*>(g_wT)[tap * Cc + c] = k[c * TAPS + (6 - i) * 7 + (6 - j)];
    }
}

__device__ __forceinline__ void ffma2(ull& d, ull a, ull b) {
    asm("fma.rn.f32x2 %0, %1, %2, %0;" : "+l"(d) : "l"(a), "l"(b));
}

// Thread tile: 4(h) x 8(w) float2 outputs for one channel pair.
// Loop over the 10 input rows; a 4-deep sliding register window of weight
// rows means each weight row is LDS'd exactly once (49 LDS / 1568 FFMA2),
// and each input row is LDG'd once (140 LDG / 1568 FFMA2).
template <bool FAST>
__device__ __forceinline__ void conv_tile(const ull* __restrict__ base,
                                          ull* __restrict__ obase,
                                          const ull* wsh,
                                          int cp, int w0, int h0) {
    ull acc[HT][WT];
    #pragma unroll
    for (int i = 0; i < HT; i++)
        #pragma unroll
        for (int j = 0; j < WT; j++) acc[i][j] = 0ull;

    ull w[4][7];   // sliding window: w[dh & 3] holds weight row dh
    int woff[WT + 6];
    if (!FAST) {
        #pragma unroll
        for (int j = 0; j < WT + 6; j++) {
            int wv = w0 - 3 + j;
            if (wv < 0) wv += Wc;
            else if (wv >= Wc) wv -= Wc;
            woff[j] = wv * CPc + cp;
        }
    }
    const ull* pfast = base + (ptrdiff_t)(h0 - 3) * (Wc * CPc) + (w0 - 3) * CPc + cp;

    #pragma unroll
    for (int r = 0; r < HT + 6; r++) {      // input row index (relative)
        ull rb[WT + 6];
        if (FAST) {
            #pragma unroll
            for (int j = 0; j < WT + 6; j++)
                rb[j] = __ldg(pfast + r * (Wc * CPc) + j * CPc);
        } else {
            int rr = h0 - 3 + r;
            if (rr < 0) rr += Hc;
            else if (rr >= Hc) rr -= Hc;
            const ull* rowp = base + (size_t)rr * (Wc * CPc);
            #pragma unroll
            for (int j = 0; j < WT + 6; j++) rb[j] = __ldg(rowp + woff[j]);
        }

        if (r <= 6) {                        // weight row r enters the window
            #pragma unroll
            for (int dw = 0; dw < 7; dw++)
                w[r & 3][dw] = wsh[(r * 7 + dw) * CPc + cp];
        }

        // input row r contributes to output rows oh with dh = r - oh in [0,6]
        #pragma unroll
        for (int oh = 0; oh < HT; oh++) {
            const int dh = r - oh;
            if (dh >= 0 && dh <= 6) {
                #pragma unroll
                for (int dw = 0; dw < 7; dw++) {
                    ull wv = w[dh & 3][dw];
                    #pragma unroll
                    for (int ow = 0; ow < WT; ow++)
                        ffma2(acc[oh][ow], wv, rb[ow + dw]);
                }
            }
        }
    }

    #pragma unroll
    for (int oh = 0; oh < HT; oh++) {
        ull* o = obase + (size_t)(h0 + oh) * (Wc * CPc) + w0 * CPc + cp;
        #pragma unroll
        for (int ow = 0; ow < WT; ow++) o[ow * CPc] = acc[oh][ow];
    }
}

__global__ __launch_bounds__(192, 2) void conv_kernel(const float* __restrict__ xf,
                                                      float* __restrict__ outf) {
    __shared__ ull wsh[TAPS * CPc];
    const int tid = threadIdx.x;
    #pragma unroll
    for (int i = tid; i < TAPS * CPc; i += 192) wsh[i] = g_wT[i];
    __syncthreads();

    const int cp    = tid % 48;
    const int ty    = tid / 48;
    const int slice = blockIdx.z;
    const int w0    = blockIdx.x * WT;
    const int h0    = blockIdx.y * (HT * 4) + ty * HT;

    const ull* base = reinterpret_cast<const ull*>(xf) + (size_t)slice * (Hc * Wc * CPc);
    ull* obase      = reinterpret_cast<ull*>(outf)     + (size_t)slice * (Hc * Wc * CPc);

    // FAST needs block input rows [by*16-3, by*16+18] and cols [bx*8-3, bx*8+10] in range
    const bool fast = (blockIdx.x >= 1) & (blockIdx.x <= (Wc / WT) - 2) &
                      (blockIdx.y >= 1) & (blockIdx.y <= (Hc / (HT * 4)) - 2);
    if (fast) conv_tile<true>(base, obase, wsh, cp, w0, h0);
    else      conv_tile<false>(base, obase, wsh, cp, w0, h0);
}

extern "C" void kernel_launch(void* const* d_in, const int* in_sizes, int n_in,
                              void* d_out, int out_size) {
    const float* x = (const float*)d_in[0];   // (2,8,224,224,96) fp32
    const float* k = (const float*)d_in[1];   // (96,1,7,7) fp32
    float* out = (float*)d_out;

    prep_kernel<<<(TAPS * Cc + 255) / 256, 256>>>(k);

    dim3 block(192);
    dim3 grid(Wc / WT, Hc / (HT * 4), 16);
    conv_kernel<<<grid, block>>>(x, out);
}

// round 13
// speedup vs baseline: 1.0042x; 1.0042x over previous
#include <cuda_runtime.h>
#include <cstdint>

#define Hc 224
#define Wc 224
#define Cc 96
#define CPc 48          // channel pairs (float2 as ull)
#define TAPS 49
#define WT 8            // per-thread output width (float2 cols)
#define HT 4            // per-thread output height

typedef unsigned long long ull;

// Flipped kernel, transposed to [tap][cp] packed float2
__device__ ull g_wT[TAPS * CPc];

__global__ void prep_kernel(const float* __restrict__ k) {
    int idx = blockIdx.x * blockDim.x + threadIdx.x;
    if (idx < TAPS * Cc) {
        int tap = idx / Cc, c = idx % Cc;
        int i = tap / 7, j = tap % 7;
        reinterpret_cast<float*>(g_wT)[tap * Cc + c] = k[c * TAPS + (6 - i) * 7 + (6 - j)];
    }
}

__device__ __forceinline__ void ffma2(ull& d, ull a, ull b) {
    asm("fma.rn.f32x2 %0, %1, %2, %0;" : "+l"(d) : "l"(a), "l"(b));
}

// Thread tile: 4(h) x 8(w) float2 outputs for one channel pair.
// Loop over the 10 input rows; a 4-deep sliding register window of weight
// rows means each weight row is LDS'd exactly once (49 LDS / 1568 FFMA2),
// and each input row is LDG'd once (140 LDG / 1568 FFMA2).
template <bool FAST>
__device__ __forceinline__ void conv_tile(const ull* __restrict__ base,
                                          ull* __restrict__ obase,
                                          const ull* wsh,
                                          int cp, int w0, int h0) {
    ull acc[HT][WT];
    #pragma unroll
    for (int i = 0; i < HT; i++)
        #pragma unroll
        for (int j = 0; j < WT; j++) acc[i][j] = 0ull;

    ull w[4][7];   // sliding window: w[dh & 3] holds weight row dh
    int woff[WT + 6];
    if (!FAST) {
        #pragma unroll
        for (int j = 0; j < WT + 6; j++) {
            int wv = w0 - 3 + j;
            if (wv < 0) wv += Wc;
            else if (wv >= Wc) wv -= Wc;
            woff[j] = wv * CPc + cp;
        }
    }
    const ull* pfast = base + (ptrdiff_t)(h0 - 3) * (Wc * CPc) + (w0 - 3) * CPc + cp;

    #pragma unroll
    for (int r = 0; r < HT + 6; r++) {      // input row index (relative)
        ull rb[WT + 6];
        if (FAST) {
            #pragma unroll
            for (int j = 0; j < WT + 6; j++)
                rb[j] = __ldg(pfast + r * (Wc * CPc) + j * CPc);
        } else {
            int rr = h0 - 3 + r;
            if (rr < 0) rr += Hc;
            else if (rr >= Hc) rr -= Hc;
            const ull* rowp = base + (size_t)rr * (Wc * CPc);
            #pragma unroll
            for (int j = 0; j < WT + 6; j++) rb[j] = __ldg(rowp + woff[j]);
        }

        if (r <= 6) {                        // weight row r enters the window
            #pragma unroll
            for (int dw = 0; dw < 7; dw++)
                w[r & 3][dw] = wsh[(r * 7 + dw) * CPc + cp];
        }

        // input row r contributes to output rows oh with dh = r - oh in [0,6]
        #pragma unroll
        for (int oh = 0; oh < HT; oh++) {
            const int dh = r - oh;
            if (dh >= 0 && dh <= 6) {
                #pragma unroll
                for (int dw = 0; dw < 7; dw++) {
                    ull wv = w[dh & 3][dw];
                    #pragma unroll
                    for (int ow = 0; ow < WT; ow++)
                        ffma2(acc[oh][ow], wv, rb[ow + dw]);
                }
            }
        }
    }

    #pragma unroll
    for (int oh = 0; oh < HT; oh++) {
        ull* o = obase + (size_t)(h0 + oh) * (Wc * CPc) + w0 * CPc + cp;
        #pragma unroll
        for (int ow = 0; ow < WT; ow++) o[ow * CPc] = acc[oh][ow];
    }
}

__global__ __launch_bounds__(192, 2) void conv_kernel(const float* __restrict__ xf,
                                                      float* __restrict__ outf) {
    __shared__ ull wsh[TAPS * CPc];
    const int tid = threadIdx.x;
    #pragma unroll
    for (int i = tid; i < TAPS * CPc; i += 192) wsh[i] = g_wT[i];
    __syncthreads();

    const int cp    = tid % 48;
    const int ty    = tid / 48;
    const int slice = blockIdx.z;
    const int w0    = blockIdx.x * WT;
    const int h0    = blockIdx.y * (HT * 4) + ty * HT;

    const ull* base = reinterpret_cast<const ull*>(xf) + (size_t)slice * (Hc * Wc * CPc);
    ull* obase      = reinterpret_cast<ull*>(outf)     + (size_t)slice * (Hc * Wc * CPc);

    // FAST needs block input rows [by*16-3, by*16+18] and cols [bx*8-3, bx*8+10] in range
    const bool fast = (blockIdx.x >= 1) & (blockIdx.x <= (Wc / WT) - 2) &
                      (blockIdx.y >= 1) & (blockIdx.y <= (Hc / (HT * 4)) - 2);
    if (fast) conv_tile<true>(base, obase, wsh, cp, w0, h0);
    else      conv_tile<false>(base, obase, wsh, cp, w0, h0);
}

extern "C" void kernel_launch(void* const* d_in, const int* in_sizes, int n_in,
                              void* d_out, int out_size) {
    const float* x = (const float*)d_in[0];   // (2,8,224,224,96) fp32
    const float* k = (const float*)d_in[1];   // (96,1,7,7) fp32
    float* out = (float*)d_out;

    prep_kernel<<<(TAPS * Cc + 255) / 256, 256>>>(k);

    dim3 block(192);
    dim3 grid(Wc / WT, Hc / (HT * 4), 16);
    conv_kernel<<<grid, block>>>(x, out);
}

// round 14
// speedup vs baseline: 1.0050x; 1.0007x over previous
#include <cuda_runtime.h>
#include <cstdint>

#define Hc 224
#define Wc 224
#define Cc 96
#define CPc 48          // channel pairs (float2 as ull)
#define TAPS 49
#define WT 8            // per-thread output width (float2 cols)
#define HT 4            // per-thread output height

typedef unsigned long long ull;

// Flipped kernel, transposed to [tap][cp] packed float2
__device__ ull g_wT[TAPS * CPc];

__global__ void prep_kernel(const float* __restrict__ k) {
    int idx = blockIdx.x * blockDim.x + threadIdx.x;
    if (idx < TAPS * Cc) {
        int tap = idx / Cc, c = idx % Cc;
        int i = tap / 7, j = tap % 7;
        reinterpret_cast<float*>(g_wT)[tap * Cc + c] = k[c * TAPS + (6 - i) * 7 + (6 - j)];
    }
}

__device__ __forceinline__ void ffma2(ull& d, ull a, ull b) {
    asm("fma.rn.f32x2 %0, %1, %2, %0;" : "+l"(d) : "l"(a), "l"(b));
}

// Thread tile: 4(h) x 8(w) float2 outputs for one channel pair.
// Loop over the 10 input rows; a 4-deep sliding register window of weight
// rows means each weight row is LDS'd exactly once (49 LDS / 1568 FFMA2),
// and each input row is LDG'd once (140 LDG / 1568 FFMA2).
template <bool FAST>
__device__ __forceinline__ void conv_tile(const ull* __restrict__ base,
                                          ull* __restrict__ obase,
                                          const ull* wsh,
                                          int cp, int w0, int h0) {
    ull acc[HT][WT];
    #pragma unroll
    for (int i = 0; i < HT; i++)
        #pragma unroll
        for (int j = 0; j < WT; j++) acc[i][j] = 0ull;

    ull w[4][7];   // sliding window: w[dh & 3] holds weight row dh
    int woff[WT + 6];
    if (!FAST) {
        #pragma unroll
        for (int j = 0; j < WT + 6; j++) {
            int wv = w0 - 3 + j;
            if (wv < 0) wv += Wc;
            else if (wv >= Wc) wv -= Wc;
            woff[j] = wv * CPc + cp;
        }
    }
    const ull* pfast = base + (ptrdiff_t)(h0 - 3) * (Wc * CPc) + (w0 - 3) * CPc + cp;

    #pragma unroll
    for (int r = 0; r < HT + 6; r++) {      // input row index (relative)
        ull rb[WT + 6];
        if (FAST) {
            #pragma unroll
            for (int j = 0; j < WT + 6; j++)
                rb[j] = __ldg(pfast + r * (Wc * CPc) + j * CPc);
        } else {
            int rr = h0 - 3 + r;
            if (rr < 0) rr += Hc;
            else if (rr >= Hc) rr -= Hc;
            const ull* rowp = base + (size_t)rr * (Wc * CPc);
            #pragma unroll
            for (int j = 0; j < WT + 6; j++) rb[j] = __ldg(rowp + woff[j]);
        }

        if (r <= 6) {                        // weight row r enters the window
            #pragma unroll
            for (int dw = 0; dw < 7; dw++)
                w[r & 3][dw] = wsh[(r * 7 + dw) * CPc + cp];
        }

        // input row r contributes to output rows oh with dh = r - oh in [0,6]
        #pragma unroll
        for (int oh = 0; oh < HT; oh++) {
            const int dh = r - oh;
            if (dh >= 0 && dh <= 6) {
                #pragma unroll
                for (int dw = 0; dw < 7; dw++) {
                    ull wv = w[dh & 3][dw];
                    #pragma unroll
                    for (int ow = 0; ow < WT; ow++)
                        ffma2(acc[oh][ow], wv, rb[ow + dw]);
                }
            }
        }
    }

    #pragma unroll
    for (int oh = 0; oh < HT; oh++) {
        ull* o = obase + (size_t)(h0 + oh) * (Wc * CPc) + w0 * CPc + cp;
        #pragma unroll
        for (int ow = 0; ow < WT; ow++) o[ow * CPc] = acc[oh][ow];
    }
}

__global__ __launch_bounds__(192, 2) void conv_kernel(const float* __restrict__ xf,
                                                      float* __restrict__ outf) {
    __shared__ ull wsh[TAPS * CPc];
    const int tid = threadIdx.x;
    #pragma unroll
    for (int i = tid; i < TAPS * CPc; i += 192) wsh[i] = g_wT[i];
    __syncthreads();

    const int cp    = tid % 48;
    const int ty    = tid / 48;
    const int slice = blockIdx.z;
    const int w0    = blockIdx.x * WT;
    const int h0    = blockIdx.y * (HT * 4) + ty * HT;

    const ull* base = reinterpret_cast<const ull*>(xf) + (size_t)slice * (Hc * Wc * CPc);
    ull* obase      = reinterpret_cast<ull*>(outf)     + (size_t)slice * (Hc * Wc * CPc);

    // FAST needs block input rows [by*16-3, by*16+18] and cols [bx*8-3, bx*8+10] in range
    const bool fast = (blockIdx.x >= 1) & (blockIdx.x <= (Wc / WT) - 2) &
                      (blockIdx.y >= 1) & (blockIdx.y <= (Hc / (HT * 4)) - 2);
    if (fast) conv_tile<true>(base, obase, wsh, cp, w0, h0);
    else      conv_tile<false>(base, obase, wsh, cp, w0, h0);
}

extern "C" void kernel_launch(void* const* d_in, const int* in_sizes, int n_in,
                              void* d_out, int out_size) {
    const float* x = (const float*)d_in[0];   // (2,8,224,224,96) fp32
    const float* k = (const float*)d_in[1];   // (96,1,7,7) fp32
    float* out = (float*)d_out;

    prep_kernel<<<(TAPS * Cc + 255) / 256, 256>>>(k);

    dim3 block(192);
    dim3 grid(Wc / WT, Hc / (HT * 4), 16);
    conv_kernel<<<grid, block>>>(x, out);
}

// round 15
// speedup vs baseline: 1.0051x; 1.0002x over previous
#include <cuda_runtime.h>
#include <cstdint>

#define Hc 224
#define Wc 224
#define Cc 96
#define CPc 48          // channel pairs (float2 as ull)
#define TAPS 49
#define WT 8            // per-thread output width (float2 cols)
#define HT 4            // per-thread output height

typedef unsigned long long ull;

// Flipped kernel, transposed to [tap][cp] packed float2
__device__ ull g_wT[TAPS * CPc];

__global__ void prep_kernel(const float* __restrict__ k) {
    int idx = blockIdx.x * blockDim.x + threadIdx.x;
    if (idx < TAPS * Cc) {
        int tap = idx / Cc, c = idx % Cc;
        int i = tap / 7, j = tap % 7;
        reinterpret_cast<float*>(g_wT)[tap * Cc + c] = k[c * TAPS + (6 - i) * 7 + (6 - j)];
    }
}

__device__ __forceinline__ void ffma2(ull& d, ull a, ull b) {
    asm("fma.rn.f32x2 %0, %1, %2, %0;" : "+l"(d) : "l"(a), "l"(b));
}

// Thread tile: 4(h) x 8(w) float2 outputs for one channel pair.
// Loop over the 10 input rows; a 4-deep sliding register window of weight
// rows means each weight row is LDS'd exactly once (49 LDS / 1568 FFMA2),
// and each input row is LDG'd once (140 LDG / 1568 FFMA2).
template <bool FAST>
__device__ __forceinline__ void conv_tile(const ull* __restrict__ base,
                                          ull* __restrict__ obase,
                                          const ull* wsh,
                                          int cp, int w0, int h0) {
    ull acc[HT][WT];
    #pragma unroll
    for (int i = 0; i < HT; i++)
        #pragma unroll
        for (int j = 0; j < WT; j++) acc[i][j] = 0ull;

    ull w[4][7];   // sliding window: w[dh & 3] holds weight row dh
    int woff[WT + 6];
    if (!FAST) {
        #pragma unroll
        for (int j = 0; j < WT + 6; j++) {
            int wv = w0 - 3 + j;
            if (wv < 0) wv += Wc;
            else if (wv >= Wc) wv -= Wc;
            woff[j] = wv * CPc + cp;
        }
    }
    const ull* pfast = base + (ptrdiff_t)(h0 - 3) * (Wc * CPc) + (w0 - 3) * CPc + cp;

    #pragma unroll
    for (int r = 0; r < HT + 6; r++) {      // input row index (relative)
        ull rb[WT + 6];
        if (FAST) {
            #pragma unroll
            for (int j = 0; j < WT + 6; j++)
                rb[j] = __ldg(pfast + r * (Wc * CPc) + j * CPc);
        } else {
            int rr = h0 - 3 + r;
            if (rr < 0) rr += Hc;
            else if (rr >= Hc) rr -= Hc;
            const ull* rowp = base + (size_t)rr * (Wc * CPc);
            #pragma unroll
            for (int j = 0; j < WT + 6; j++) rb[j] = __ldg(rowp + woff[j]);
        }

        if (r <= 6) {                        // weight row r enters the window
            #pragma unroll
            for (int dw = 0; dw < 7; dw++)
                w[r & 3][dw] = wsh[(r * 7 + dw) * CPc + cp];
        }

        // input row r contributes to output rows oh with dh = r - oh in [0,6]
        #pragma unroll
        for (int oh = 0; oh < HT; oh++) {
            const int dh = r - oh;
            if (dh >= 0 && dh <= 6) {
                #pragma unroll
                for (int dw = 0; dw < 7; dw++) {
                    ull wv = w[dh & 3][dw];
                    #pragma unroll
                    for (int ow = 0; ow < WT; ow++)
                        ffma2(acc[oh][ow], wv, rb[ow + dw]);
                }
            }
        }
    }

    #pragma unroll
    for (int oh = 0; oh < HT; oh++) {
        ull* o = obase + (size_t)(h0 + oh) * (Wc * CPc) + w0 * CPc + cp;
        #pragma unroll
        for (int ow = 0; ow < WT; ow++) o[ow * CPc] = acc[oh][ow];
    }
}

__global__ __launch_bounds__(192, 2) void conv_kernel(const float* __restrict__ xf,
                                                      float* __restrict__ outf) {
    __shared__ ull wsh[TAPS * CPc];
    const int tid = threadIdx.x;
    #pragma unroll
    for (int i = tid; i < TAPS * CPc; i += 192) wsh[i] = g_wT[i];
    __syncthreads();

    const int cp    = tid % 48;
    const int ty    = tid / 48;
    const int slice = blockIdx.z;
    const int w0    = blockIdx.x * WT;
    const int h0    = blockIdx.y * (HT * 4) + ty * HT;

    const ull* base = reinterpret_cast<const ull*>(xf) + (size_t)slice * (Hc * Wc * CPc);
    ull* obase      = reinterpret_cast<ull*>(outf)     + (size_t)slice * (Hc * Wc * CPc);

    // FAST needs block input rows [by*16-3, by*16+18] and cols [bx*8-3, bx*8+10] in range
    const bool fast = (blockIdx.x >= 1) & (blockIdx.x <= (Wc / WT) - 2) &
                      (blockIdx.y >= 1) & (blockIdx.y <= (Hc / (HT * 4)) - 2);
    if (fast) conv_tile<true>(base, obase, wsh, cp, w0, h0);
    else      conv_tile<false>(base, obase, wsh, cp, w0, h0);
}

extern "C" void kernel_launch(void* const* d_in, const int* in_sizes, int n_in,
                              void* d_out, int out_size) {
    const float* x = (const float*)d_in[0];   // (2,8,224,224,96) fp32
    const float* k = (const float*)d_in[1];   // (96,1,7,7) fp32
    float* out = (float*)d_out;

    prep_kernel<<<(TAPS * Cc + 255) / 256, 256>>>(k);

    dim3 block(192);
    dim3 grid(Wc / WT, Hc / (HT * 4), 16);
    conv_kernel<<<grid, block>>>(x, out);
}